// round 4
// baseline (speedup 1.0000x reference)
#include <cuda_runtime.h>
#include <cstdint>

#define NB   8
#define CCH  256      // channels
#define SP   4096     // spatial positions per batch (16^3)
#define NROW 32768    // NB*SP
#define KCB  1024     // codebook size

#define ZQ_SIZE   8388608
#define LOSS_OFF  8388608
#define PERP_OFF  8388609
#define IDX_OFF   8388610
#define FULL_OUT  8421378

__device__ float  g_S[NROW];       // |z_n|^2 (fp32)
__device__ float  g_esq[KCB];      // |e_k|^2 (fp32)
__device__ int    g_idx[NROW];
__device__ int    g_counts[KCB];
__device__ double g_losspart[1024];

// ---------------------------------------------------------------------------
// Kernel A: per-row |z|^2, per-code |e|^2, zero counts
// ---------------------------------------------------------------------------
__global__ void prep_kernel(const float* __restrict__ z,
                            const float* __restrict__ emb) {
    int bi  = blockIdx.x;
    int tid = threadIdx.x;
    if (bi < 128) {
        // 256 rows per block, coalesced over s
        int n0 = bi * 256;
        int b  = n0 >> 12;
        int s  = (n0 & 4095) + tid;
        const float* zb = z + (size_t)b * CCH * SP + s;
        float acc = 0.f;
        #pragma unroll 8
        for (int c = 0; c < CCH; c++) {
            float v = zb[(size_t)c * SP];
            acc = __fmaf_rn(v, v, acc);
        }
        g_S[n0 + tid] = acc;
    } else if (bi < 132) {
        int k = (bi - 128) * 256 + tid;
        const float* er = emb + (size_t)k * CCH;
        float acc = 0.f;
        #pragma unroll 8
        for (int c = 0; c < CCH; c++) {
            float v = er[c];
            acc = __fmaf_rn(v, v, acc);
        }
        g_esq[k] = acc;
    } else {
        // FIX (R3): zero ALL KCB counts, not just the first 256.
        // Replay-idempotency: stale counts[256..1023] made perplexity -> inf.
        for (int k = tid; k < KCB; k += 256) g_counts[k] = 0;
    }
}

// ---------------------------------------------------------------------------
// Kernel B: distance GEMM + argmin
//   block: 256 threads = 16 (k-dir) x 16 (s-dir), thread tile 8s x 8k
//   block tile: 128 s-rows, k streamed in chunks of 128, c in chunks of 16
// ---------------------------------------------------------------------------
#define BS 128
#define BK 128
#define TC 16

__device__ __forceinline__ unsigned int float_key(float f) {
    unsigned int u = __float_as_uint(f);
    return (u & 0x80000000u) ? ~u : (u | 0x80000000u);
}

__global__ __launch_bounds__(256, 2)
void argmin_kernel(const float* __restrict__ z,
                   const float* __restrict__ emb) {
    __shared__ float zs[TC][BS];
    __shared__ float es[TC][BK];
    __shared__ unsigned long long best[BS];

    int tid = threadIdx.x;
    int n0  = blockIdx.x * BS;
    int b   = n0 >> 12;
    int s0  = n0 & 4095;
    int kt  = tid & 15;        // k-group
    int st  = tid >> 4;        // s-group

    if (tid < BS) best[tid] = 0xFFFFFFFFFFFFFFFFULL;

    float Ss[8];
    #pragma unroll
    for (int i = 0; i < 8; i++) Ss[i] = g_S[n0 + st * 8 + i];

    const float* zb = z + (size_t)b * CCH * SP + s0;

    for (int kc = 0; kc < KCB / BK; kc++) {
        int k0 = kc * BK;
        float acc[8][8];
        #pragma unroll
        for (int i = 0; i < 8; i++)
            #pragma unroll
            for (int j = 0; j < 8; j++) acc[i][j] = 0.f;

        #pragma unroll 1
        for (int cc = 0; cc < CCH / TC; cc++) {
            int c0 = cc * TC;
            __syncthreads();
            // load z chunk [TC x BS], coalesced float4 over s
            #pragma unroll
            for (int i = tid; i < (TC * BS) / 4; i += 256) {
                int c  = i >> 5;
                int sq = i & 31;
                float4 v = *(const float4*)(zb + (size_t)(c0 + c) * SP + sq * 4);
                *(float4*)&zs[c][sq * 4] = v;
            }
            // load e chunk [BK x TC] transposed -> es[c][k]
            #pragma unroll
            for (int i = tid; i < (BK * TC) / 4; i += 256) {
                int kk = i >> 2;
                int cq = i & 3;
                float4 v = *(const float4*)(emb + (size_t)(k0 + kk) * CCH + c0 + cq * 4);
                es[cq * 4 + 0][kk] = v.x;
                es[cq * 4 + 1][kk] = v.y;
                es[cq * 4 + 2][kk] = v.z;
                es[cq * 4 + 3][kk] = v.w;
            }
            __syncthreads();

            #pragma unroll
            for (int c = 0; c < TC; c++) {
                float zr[8], er[8];
                *(float4*)&zr[0] = *(const float4*)&zs[c][st * 8];
                *(float4*)&zr[4] = *(const float4*)&zs[c][st * 8 + 4];
                *(float4*)&er[0] = *(const float4*)&es[c][kt * 8];
                *(float4*)&er[4] = *(const float4*)&es[c][kt * 8 + 4];
                #pragma unroll
                for (int i = 0; i < 8; i++)
                    #pragma unroll
                    for (int j = 0; j < 8; j++)
                        acc[i][j] = __fmaf_rn(zr[i], er[j], acc[i][j]);
            }
        }

        // epilogue for this k-chunk: d = fl(fl(S+esq) - 2m), local then shared argmin
        float eq[8];
        #pragma unroll
        for (int j = 0; j < 8; j++) eq[j] = g_esq[k0 + kt * 8 + j];

        #pragma unroll
        for (int i = 0; i < 8; i++) {
            float bv = __int_as_float(0x7f800000); // +inf
            int   bk = 0;
            #pragma unroll
            for (int j = 0; j < 8; j++) {
                float t = __fadd_rn(Ss[i], eq[j]);          // fl(S + esq)
                float v = __fmaf_rn(-2.0f, acc[i][j], t);   // fl(t - 2m), one rounding
                if (v < bv) { bv = v; bk = k0 + kt * 8 + j; }
            }
            unsigned long long key =
                ((unsigned long long)float_key(bv) << 32) | (unsigned int)bk;
            atomicMin(&best[st * 8 + i], key);
        }
    }

    __syncthreads();
    if (tid < BS) {
        g_idx[n0 + tid] = (int)(best[tid] & 0xFFFFFFFFu);
    }
}

// ---------------------------------------------------------------------------
// Kernel C: STE output, counts, loss partial sums (deterministic per-block slot)
//   1024 blocks x 256 threads, 32 s-rows per block
// ---------------------------------------------------------------------------
__global__ __launch_bounds__(256)
void epilogue_kernel(const float* __restrict__ z,
                     const float* __restrict__ emb,
                     float* __restrict__ out,
                     int has_extras) {
    __shared__ float  es[32][257];   // padded: avoids 32-way conflict on column reads
    __shared__ int    sidx[32];
    __shared__ double red[256];

    int tid = threadIdx.x;
    int n0  = blockIdx.x * 32;
    int b   = n0 >> 12;
    int s0  = n0 & 4095;

    if (tid < 32) sidx[tid] = g_idx[n0 + tid];
    __syncthreads();

    // gather 32 embedding rows into smem
    for (int i = tid; i < 32 * 64; i += 256) {
        int r = i >> 6;
        int q = i & 63;
        float4 v = *(const float4*)(emb + (size_t)sidx[r] * CCH + q * 4);
        es[r][q * 4 + 0] = v.x;
        es[r][q * 4 + 1] = v.y;
        es[r][q * 4 + 2] = v.z;
        es[r][q * 4 + 3] = v.w;
    }
    if (tid < 32) atomicAdd(&g_counts[sidx[tid]], 1);
    __syncthreads();

    int s  = tid & 31;
    int cb = tid >> 5;   // 8 channel lanes
    const float* zb = z   + (size_t)b * CCH * SP + s0;
    float*       ob = out + (size_t)b * CCH * SP + s0;

    float lacc = 0.f;
    #pragma unroll 4
    for (int c0 = 0; c0 < CCH; c0 += 8) {
        int c = c0 + cb;
        float zv = zb[(size_t)c * SP + s];
        float ev = es[s][c];
        float d  = __fadd_rn(ev, -zv);        // fl(z_q - z)
        lacc = __fmaf_rn(d, d, lacc);
        ob[(size_t)c * SP + s] = __fadd_rn(zv, d);   // STE: fl(z + fl(z_q - z))
    }

    if (has_extras && tid < 32) {
        out[IDX_OFF + n0 + tid] = (float)sidx[tid];
    }

    red[tid] = (double)lacc;
    __syncthreads();
    for (int off = 128; off > 0; off >>= 1) {
        if (tid < off) red[tid] += red[tid + off];
        __syncthreads();
    }
    if (tid == 0) g_losspart[blockIdx.x] = red[0];
}

// ---------------------------------------------------------------------------
// Kernel D: final loss + perplexity (deterministic tree reductions)
// ---------------------------------------------------------------------------
__global__ __launch_bounds__(1024)
void finalize_kernel(float* __restrict__ out, int has_extras) {
    __shared__ double sd[1024];
    int tid = threadIdx.x;

    // entropy term
    {
        int   cnt = g_counts[tid];
        float em  = (float)cnt * (1.0f / 32768.0f);   // exact /32768
        float t   = em * logf(em + 1e-10f);
        sd[tid] = (double)t;
    }
    __syncthreads();
    for (int off = 512; off > 0; off >>= 1) {
        if (tid < off) sd[tid] += sd[tid + off];
        __syncthreads();
    }
    float perplexity = expf(-(float)sd[0]);
    __syncthreads();

    // loss
    sd[tid] = g_losspart[tid];
    __syncthreads();
    for (int off = 512; off > 0; off >>= 1) {
        if (tid < off) sd[tid] += sd[tid + off];
        __syncthreads();
    }
    if (tid == 0 && has_extras) {
        double mean = sd[0] / (double)ZQ_SIZE;
        float  m    = (float)mean;
        float  loss = __fadd_rn(m, 0.25f * m);   // legacy: m1 + beta*m2, m1==m2
        out[LOSS_OFF] = loss;
        out[PERP_OFF] = perplexity;
    }
}

// ---------------------------------------------------------------------------
extern "C" void kernel_launch(void* const* d_in, const int* in_sizes, int n_in,
                              void* d_out, int out_size) {
    const float* z   = (const float*)d_in[0];
    const float* emb = (const float*)d_in[1];
    float* out = (float*)d_out;
    int has_extras = (out_size >= FULL_OUT) ? 1 : 0;

    prep_kernel<<<133, 256>>>(z, emb);
    argmin_kernel<<<NROW / BS, 256>>>(z, emb);
    epilogue_kernel<<<NROW / 32, 256>>>(z, emb, out, has_extras);
    finalize_kernel<<<1, 1024>>>(out, has_extras);
}